// round 6
// baseline (speedup 1.0000x reference)
#include <cuda_runtime.h>
#include <cuda_fp16.h>
#include <cstdint>

#define H     1024
#define FH    4096
#define V     32000
#define SEQ   2048
#define GRID  148
#define NT    1024
#define NW    32
#define TW    (GRID * NW)
#define NROWS (V + 2 * FH)

// ---------------- device globals (static, no allocation) ----------------
__device__ __align__(16) __half g_wfc16[(size_t)V * H];  // 64 MB fp16 copy of w_fc
__device__ float g_hh0[FH];        // whh0 @ h0_t + b_ih0 + b_hh0
__device__ float g_hh1[2][FH];     // whh1 @ h1_t (double buffered)
__device__ float g_ih1[FH];        // wih1 @ h0_t + b_ih1 + b_hh1
__device__ unsigned g_flag[GRID];  // per-block barrier arrival counters (monotonic)
__device__ unsigned g_relg;        // barrier release counter (monotonic)
__device__ unsigned g_done[GRID];  // per-block fc-done counters (monotonic)
__device__ unsigned long long g_tok; // (doneCount<<32) | tokenIdx

// ---------------- fp32 row dot (warp collective, result on lane 0) -------
__device__ __forceinline__ float dot1024(const float* __restrict__ w,
                                         const float4* __restrict__ hv,
                                         int lane) {
    const float4* wv = (const float4*)w;
    float acc = 0.f;
    #pragma unroll
    for (int k = 0; k < 8; ++k) {
        float4 a = wv[lane + 32 * k];
        float4 b = hv[lane + 32 * k];
        acc = fmaf(a.x, b.x, acc); acc = fmaf(a.y, b.y, acc);
        acc = fmaf(a.z, b.z, acc); acc = fmaf(a.w, b.w, acc);
    }
    #pragma unroll
    for (int off = 16; off; off >>= 1)
        acc += __shfl_down_sync(0xffffffffu, acc, off);
    return acc;
}

__device__ __forceinline__ float sigm(float v) { return 1.f / (1.f + expf(-v)); }

// ---------------- fp32 -> fp16 conversion prologue kernel ----------------
__global__ void conv_kernel(const float* __restrict__ wfc) {
    const size_t n4 = (size_t)V * H / 4;
    const float4* src = (const float4*)wfc;
    for (size_t i = (size_t)blockIdx.x * blockDim.x + threadIdx.x;
         i < n4; i += (size_t)gridDim.x * blockDim.x) {
        float4 v = __ldcs(&src[i]);
        __half2 a = __floats2half2_rn(v.x, v.y);
        __half2 b = __floats2half2_rn(v.z, v.w);
        uint2 o;
        o.x = *(unsigned*)&a;
        o.y = *(unsigned*)&b;
        *(uint2*)(&g_wfc16[4 * i]) = o;
    }
}

// ---------------- main persistent kernel ----------------
__global__ void __launch_bounds__(NT, 1)
decoder_kernel(const int*   __restrict__ y,
               const float* __restrict__ ctx,
               const float* __restrict__ wih0,
               const float* __restrict__ whh0,
               const float* __restrict__ bih0,
               const float* __restrict__ bhh0,
               const float* __restrict__ wih1,
               const float* __restrict__ whh1,
               const float* __restrict__ bih1,
               const float* __restrict__ bhh1,
               const float* __restrict__ wfc,
               const float* __restrict__ bfc,
               float* __restrict__ out)
{
    __shared__ __align__(16) float hs0[H];
    __shared__ __align__(16) float hs1[H];
    __shared__ float cs0[H];
    __shared__ float cs1[H];
    __shared__ float sWih0[FH];        // wih0 column cached in smem (16 KB)
    __shared__ float sRed[NW];
    __shared__ float sTok;
    __shared__ int   sCand[32];
    __shared__ int   sCnt;
    __shared__ unsigned long long sBest;
    __shared__ float sMax;

    const int tid  = threadIdx.x;
    const int lane = tid & 31;
    const int warp = tid >> 5;
    const int bid  = blockIdx.x;
    const int gw   = bid * NW + warp;

    // replay-safe bases: each block reads only its OWN flags (no races)
    unsigned barCnt  = g_flag[bid];
    unsigned doneCnt = g_done[bid];

    // init state (redundant per block) + smem caches
    hs0[tid] = cs0[tid] = ctx[tid];
    hs1[tid] = cs1[tid] = ctx[H + tid];
    #pragma unroll
    for (int j = 0; j < 4; ++j)
        sWih0[tid + j * NT] = wih0[tid + j * NT];
    __syncthreads();

    const float4* h0v = (const float4*)hs0;
    const float4* h1v = (const float4*)hs1;

    // out row 0 = zeros
    for (int i = bid * NT + tid; i < V; i += GRID * NT)
        out[i] = 0.0f;

    // prologue: hh matvecs on the initial context
    for (int idx = gw; idx < 2 * FH; idx += TW) {
        if (idx < FH) {
            float acc = dot1024(whh0 + (size_t)idx * H, h0v, lane);
            if (lane == 0) g_hh0[idx] = acc + bih0[idx] + bhh0[idx];
        } else {
            int r = idx - FH;
            float acc = dot1024(whh1 + (size_t)r * H, h1v, lane);
            if (lane == 0) g_hh1[1][r] = acc;
        }
    }

    // ---- barrier (flag-based) ----
    auto gsync = [&](unsigned target) {
        __syncthreads();
        if (bid == 0) {
            if (tid < 32) {
                if (tid == 0) { __threadfence(); ((volatile unsigned*)g_flag)[0] = target; }
                bool done = false;
                while (!done) {
                    bool mine = true;
                    for (int i = tid; i < GRID; i += 32)
                        if (((volatile unsigned*)g_flag)[i] < target) mine = false;
                    done = __all_sync(0xffffffffu, mine);
                }
                if (tid == 0) { __threadfence(); ((volatile unsigned*)&g_relg)[0] = target; }
            }
        } else if (tid == 0) {
            __threadfence();
            ((volatile unsigned*)g_flag)[bid] = target;
            while (((volatile unsigned*)&g_relg)[0] < target) { }
            __threadfence();
        }
        __syncthreads();
    };

    gsync(++barCnt);

    const float y0f = (float)__ldg(&y[0]);

    for (int t = 0; t < SEQ - 1; ++t) {
        // ---------- token acquire ----------
        float x;
        if (t == 0) {
            x = y0f;
        } else if (bid == 0) {
            x = sTok;                 // set by this block at end of previous iter
        } else {
            if (tid == 0) {
                unsigned target = doneCnt;      // == doneBase + t
                unsigned long long v;
                do { v = *((volatile unsigned long long*)&g_tok); }
                while ((unsigned)(v >> 32) < target);
                sTok = (float)(int)(unsigned)(v & 0xffffffffu);
                __threadfence();
            }
            __syncthreads();
            x = sTok;
        }

        // ---------- cell 0 (redundant per block) ----------
        {
            float gi = __ldg(&g_hh0[tid])         + sWih0[tid]         * x;
            float gf = __ldg(&g_hh0[tid + H])     + sWih0[tid + H]     * x;
            float gg = __ldg(&g_hh0[tid + 2 * H]) + sWih0[tid + 2 * H] * x;
            float go = __ldg(&g_hh0[tid + 3 * H]) + sWih0[tid + 3 * H] * x;
            float c  = sigm(gf) * cs0[tid] + sigm(gi) * tanhf(gg);
            cs0[tid] = c;
            hs0[tid] = sigm(go) * tanhf(c);
        }
        __syncthreads();

        // ---------- wih1 @ h0_t -> g_ih1 ----------
        for (int row = gw; row < FH; row += TW) {
            float acc = dot1024(wih1 + (size_t)row * H, h0v, lane);
            if (lane == 0) g_ih1[row] = acc + bih1[row] + bhh1[row];
        }
        gsync(++barCnt);

        // ---------- cell 1 (redundant per block) ----------
        {
            const float* hh1 = g_hh1[(t + 1) & 1];
            float gi = __ldg(&hh1[tid])         + __ldg(&g_ih1[tid]);
            float gf = __ldg(&hh1[tid + H])     + __ldg(&g_ih1[tid + H]);
            float gg = __ldg(&hh1[tid + 2 * H]) + __ldg(&g_ih1[tid + 2 * H]);
            float go = __ldg(&hh1[tid + 3 * H]) + __ldg(&g_ih1[tid + 3 * H]);
            float c  = sigm(gf) * cs1[tid] + sigm(gi) * tanhf(gg);
            cs1[tid] = c;
            hs1[tid] = sigm(go) * tanhf(c);
        }
        __syncthreads();

        // ---------- fused: fc (fp16, L2) + whh0@h0_t + whh1@h1_t ----------
        float* orow = out + (size_t)(t + 1) * V;
        float* hh1w = g_hh1[t & 1];
        for (int idx = gw; idx < NROWS; idx += TW) {
            if (idx < V) {
                // fp16 row dot: each uint4 = 8 halves = 4 half2 pairs with 2 float4 of h1
                const uint4* wr = (const uint4*)(g_wfc16 + (size_t)idx * H);  // 128 uint4
                float acc = 0.f;
                #pragma unroll
                for (int k = 0; k < 4; ++k) {
                    uint4 u = __ldg(&wr[lane + 32 * k]);
                    const __half2* hp = (const __half2*)&u;   // hp[0..3]
                    const float4* hb = h1v + 2 * (lane + 32 * k);
                    float4 ha = hb[0];
                    float4 hc = hb[1];
                    float2 w0 = __half22float2(hp[0]);
                    float2 w1 = __half22float2(hp[1]);
                    float2 w2 = __half22float2(hp[2]);
                    float2 w3 = __half22float2(hp[3]);
                    acc = fmaf(w0.x, ha.x, acc); acc = fmaf(w0.y, ha.y, acc);
                    acc = fmaf(w1.x, ha.z, acc); acc = fmaf(w1.y, ha.w, acc);
                    acc = fmaf(w2.x, hc.x, acc); acc = fmaf(w2.y, hc.y, acc);
                    acc = fmaf(w3.x, hc.z, acc); acc = fmaf(w3.y, hc.w, acc);
                }
                #pragma unroll
                for (int off = 16; off; off >>= 1)
                    acc += __shfl_down_sync(0xffffffffu, acc, off);
                if (lane == 0)
                    orow[idx] = fmaxf(acc + bfc[idx], 0.0f);
            } else if (idx < V + FH) {
                int r = idx - V;
                float acc = dot1024(whh0 + (size_t)r * H, h0v, lane);
                if (lane == 0) g_hh0[r] = acc + bih0[r] + bhh0[r];
            } else {
                int r = idx - V - FH;
                float acc = dot1024(whh1 + (size_t)r * H, h1v, lane);
                if (lane == 0) hh1w[r] = acc;
            }
        }

        // ---------- fc done publish ----------
        __syncthreads();
        ++doneCnt;
        if (tid == 0) {
            __threadfence();
            ((volatile unsigned*)g_done)[bid] = doneCnt;
        }

        // ---------- block 0: scan preds, exact fp32 argmax, publish token ----------
        if (bid == 0 && t < SEQ - 2) {
            if (tid < 32) {
                bool done = false;
                while (!done) {
                    bool mine = true;
                    for (int i = tid; i < GRID; i += 32)
                        if (((volatile unsigned*)g_done)[i] < doneCnt) mine = false;
                    done = __all_sync(0xffffffffu, mine);
                }
            }
            __syncthreads();
            __threadfence();

            // pass 1: approx pred max
            const float4* pv = (const float4*)orow;
            float m = 0.f;
            #pragma unroll
            for (int k = 0; k < 8; ++k) {
                int i4 = tid + k * NT;
                if (i4 < V / 4) {
                    float4 v = __ldcg(&pv[i4]);
                    m = fmaxf(m, fmaxf(fmaxf(v.x, v.y), fmaxf(v.z, v.w)));
                }
            }
            #pragma unroll
            for (int off = 16; off; off >>= 1)
                m = fmaxf(m, __shfl_down_sync(0xffffffffu, m, off));
            if (lane == 0) sRed[warp] = m;
            __syncthreads();
            if (tid == 0) {
                float mm = 0.f;
                #pragma unroll
                for (int w = 0; w < NW; ++w) mm = fmaxf(mm, sRed[w]);
                sMax = mm; sCnt = 0; sBest = 0ull;
            }
            __syncthreads();

            // pass 2: collect candidates within conservative fp16-error bound
            float cutoff = sMax - (0.02f * fmaxf(sMax, 1.0f) + 0.005f);
            #pragma unroll
            for (int k = 0; k < 8; ++k) {
                int i4 = tid + k * NT;
                if (i4 < V / 4) {
                    float4 v = __ldcg(&pv[i4]);
                    float vv[4] = {v.x, v.y, v.z, v.w};
                    #pragma unroll
                    for (int c = 0; c < 4; ++c) {
                        if (vv[c] >= cutoff) {
                            int pos = atomicAdd(&sCnt, 1);
                            if (pos < 32) sCand[pos] = 4 * i4 + c;
                        }
                    }
                }
            }
            __syncthreads();

            // pass 3: fp32 recompute candidates (one per warp), exact argmax
            int ncand = sCnt < 32 ? sCnt : 32;
            for (int c = warp; c < ncand; c += NW) {
                int row = sCand[c];
                float acc = dot1024(wfc + (size_t)row * H, h1v, lane);
                if (lane == 0) {
                    float val = fmaxf(acc + bfc[row], 0.0f);
                    unsigned long long key =
                        ((unsigned long long)__float_as_uint(val) << 32) |
                        (unsigned)(0x7fffffff - row);
                    atomicMax(&sBest, key);
                }
            }
            __syncthreads();
            if (tid == 0) {
                int best = 0x7fffffff - (int)(unsigned)(sBest & 0xffffffffu);
                sTok = (float)best;
                __threadfence();
                *((volatile unsigned long long*)&g_tok) =
                    ((unsigned long long)doneCnt << 32) | (unsigned)best;
            }
            __syncthreads();
        }
    }
}

extern "C" void kernel_launch(void* const* d_in, const int* in_sizes, int n_in,
                              void* d_out, int out_size) {
    const int*   y    = (const int*)  d_in[0];
    const float* ctx  = (const float*)d_in[1];
    const float* wih0 = (const float*)d_in[2];
    const float* whh0 = (const float*)d_in[3];
    const float* bih0 = (const float*)d_in[4];
    const float* bhh0 = (const float*)d_in[5];
    const float* wih1 = (const float*)d_in[6];
    const float* whh1 = (const float*)d_in[7];
    const float* bih1 = (const float*)d_in[8];
    const float* bhh1 = (const float*)d_in[9];
    const float* wfc  = (const float*)d_in[10];
    const float* bfc  = (const float*)d_in[11];
    float* out = (float*)d_out;

    conv_kernel<<<1024, 256>>>(wfc);
    decoder_kernel<<<GRID, NT>>>(y, ctx, wih0, whh0, bih0, bhh0,
                                 wih1, whh1, bih1, bhh1, wfc, bfc, out);
}

// round 8
// speedup vs baseline: 1.3645x; 1.3645x over previous
#include <cuda_runtime.h>
#include <cuda_fp16.h>
#include <cstdint>

#define H     1024
#define FH    4096
#define V     32000
#define SEQ   2048
#define GRID  148
#define NT    1024
#define NW    32
#define TW    (GRID * NW)
#define EPB   7                  // h1 entries owned per block (148*7 >= 1024)
#define GW1   (4 * EPB)          // gate rows cached per block (28)

// ---------------- device globals (static, no allocation) ----------------
__device__ __align__(16) __half g_wfc16[(size_t)V * H];  // 64 MB fp16 copy of w_fc
__device__ float g_hh0[FH];        // whh0 @ h0_t + b_ih0 + b_hh0
__device__ float g_hh1[2][FH];     // whh1 @ h1_t (double buffered)
__device__ float g_h1[H];          // published h1_t
__device__ unsigned long long g_part[GRID];  // per-block exact argmax partial
__device__ unsigned g_flag[GRID];  // barrier arrival counters (monotonic)
__device__ unsigned g_relg;        // barrier release (monotonic)
__device__ unsigned g_done[GRID];  // per-block step-done counters (monotonic)

// ---------------- fp32 row dot (warp collective, result on lane 0) -------
__device__ __forceinline__ float dot1024(const float* __restrict__ w,
                                         const float4* __restrict__ hv,
                                         int lane) {
    const float4* wv = (const float4*)w;
    float acc = 0.f;
    #pragma unroll
    for (int k = 0; k < 8; ++k) {
        float4 a = wv[lane + 32 * k];
        float4 b = hv[lane + 32 * k];
        acc = fmaf(a.x, b.x, acc); acc = fmaf(a.y, b.y, acc);
        acc = fmaf(a.z, b.z, acc); acc = fmaf(a.w, b.w, acc);
    }
    #pragma unroll
    for (int off = 16; off; off >>= 1)
        acc += __shfl_down_sync(0xffffffffu, acc, off);
    return acc;
}

__device__ __forceinline__ float sigm(float v) { return 1.f / (1.f + expf(-v)); }

// ---------------- fp32 -> fp16 conversion prologue kernel ----------------
__global__ void conv_kernel(const float* __restrict__ wfc) {
    const size_t n4 = (size_t)V * H / 4;
    const float4* src = (const float4*)wfc;
    for (size_t i = (size_t)blockIdx.x * blockDim.x + threadIdx.x;
         i < n4; i += (size_t)gridDim.x * blockDim.x) {
        float4 v = __ldcs(&src[i]);
        __half2 a = __floats2half2_rn(v.x, v.y);
        __half2 b = __floats2half2_rn(v.z, v.w);
        uint2 o;
        o.x = *(unsigned*)&a;
        o.y = *(unsigned*)&b;
        *(uint2*)(&g_wfc16[4 * i]) = o;
    }
}

// ---------------- main persistent kernel ----------------
__global__ void __launch_bounds__(NT, 1)
decoder_kernel(const int*   __restrict__ y,
               const float* __restrict__ ctx,
               const float* __restrict__ wih0,
               const float* __restrict__ whh0,
               const float* __restrict__ bih0,
               const float* __restrict__ bhh0,
               const float* __restrict__ wih1,
               const float* __restrict__ whh1,
               const float* __restrict__ bih1,
               const float* __restrict__ bhh1,
               const float* __restrict__ wfc,
               const float* __restrict__ bfc,
               float* __restrict__ out)
{
    extern __shared__ __align__(16) float dyn[];
    float* hs0   = dyn;              // [1024]
    float* hs1   = dyn + 1024;       // [1024]
    float* cs0   = dyn + 2048;       // [1024]
    float* sWih0 = dyn + 3072;       // [4096]
    float* sW1   = dyn + 7168;       // [28][1024] owned wih1 gate rows

    __shared__ float sRed[NW];
    __shared__ float sG[GW1];        // owned layer-1 gate values
    __shared__ float sB1[GW1];       // folded biases for owned rows
    __shared__ float sC1[EPB];       // owned c1 state
    __shared__ float sTok;
    __shared__ float sMax;
    __shared__ int   sCnt;
    __shared__ int   sCand[64];
    __shared__ unsigned long long sBest;

    const int tid  = threadIdx.x;
    const int lane = tid & 31;
    const int warp = tid >> 5;
    const int bid  = blockIdx.x;
    const int gw   = bid * NW + warp;
    const int o0   = bid * EPB;

    // replay-safe bases (each block reads only its OWN counters)
    unsigned barCnt  = g_flag[bid];
    unsigned doneBase = g_done[bid];

    // ---- init smem state ----
    hs0[tid] = cs0[tid] = ctx[tid];
    hs1[tid] = ctx[H + tid];
    #pragma unroll
    for (int j = 0; j < 4; ++j)
        sWih0[tid + j * NT] = wih0[tid + j * NT];
    if (tid < EPB && o0 + tid < H) sC1[tid] = ctx[H + o0 + tid];
    if (tid < GW1) {
        int e = tid >> 2, g = tid & 3;
        int row = (o0 + e) + g * H;
        sB1[tid] = (o0 + e < H) ? (bih1[row] + bhh1[row]) : 0.f;
    }
    // cache owned wih1 rows into smem
    for (int w = 0; w < GW1; ++w) {
        int e = w >> 2, g = w & 3;
        if (o0 + e < H) {
            const float* src = wih1 + (size_t)((o0 + e) + g * H) * H;
            sW1[w * H + tid] = src[tid];
        }
    }
    __syncthreads();

    const float4* h0v = (const float4*)hs0;
    const float4* h1v = (const float4*)hs1;

    // out row 0 = zeros
    for (int i = bid * NT + tid; i < V; i += GRID * NT)
        out[i] = 0.0f;

    // prologue: whh0@ctx0 -> g_hh0 (+b0 folded) ; whh1@ctx1 -> g_hh1[1]
    for (int idx = gw; idx < 2 * FH; idx += TW) {
        if (idx < FH) {
            float acc = dot1024(whh0 + (size_t)idx * H, h0v, lane);
            if (lane == 0) __stcg(&g_hh0[idx], acc + bih0[idx] + bhh0[idx]);
        } else {
            int r = idx - FH;
            float acc = dot1024(whh1 + (size_t)r * H, h1v, lane);
            if (lane == 0) __stcg(&g_hh1[1][r], acc);
        }
    }

    // ---- flag-based barrier ----
    auto gsync = [&](unsigned target) {
        __syncthreads();
        if (bid == 0) {
            if (tid < 32) {
                if (tid == 0) { __threadfence(); ((volatile unsigned*)g_flag)[0] = target; }
                bool done = false;
                while (!done) {
                    bool mine = true;
                    for (int i = tid; i < GRID; i += 32)
                        if (((volatile unsigned*)g_flag)[i] < target) mine = false;
                    done = __all_sync(0xffffffffu, mine);
                }
                if (tid == 0) { __threadfence(); ((volatile unsigned*)&g_relg)[0] = target; }
            }
        } else if (tid == 0) {
            __threadfence();
            ((volatile unsigned*)g_flag)[bid] = target;
            while (((volatile unsigned*)&g_relg)[0] < target) { }
            __threadfence();
        }
        __syncthreads();
    };

    gsync(++barCnt);

    const float y0f = (float)__ldg(&y[0]);

    for (int t = 0; t < SEQ - 1; ++t) {
        // ---------- token: done-barrier + decentralized combine ----------
        float x;
        if (t == 0) {
            x = y0f;
        } else {
            if (tid < 32) {
                unsigned target = doneBase + (unsigned)t;
                bool done = false;
                while (!done) {
                    bool mine = true;
                    for (int i = lane; i < GRID; i += 32)
                        if (((volatile unsigned*)g_done)[i] < target) mine = false;
                    done = __all_sync(0xffffffffu, mine);
                }
                unsigned long long best = 0ull;
                for (int i = lane; i < GRID; i += 32) {
                    unsigned long long v = __ldcg(&g_part[i]);
                    if (v > best) best = v;
                }
                #pragma unroll
                for (int off = 16; off; off >>= 1) {
                    unsigned long long o = __shfl_down_sync(0xffffffffu, best, off);
                    if (o > best) best = o;
                }
                if (lane == 0)
                    sTok = (float)(0x7fffffff - (int)(unsigned)(best & 0xffffffffu));
            }
            __syncthreads();
            x = sTok;
        }

        // ---------- cell 0 (redundant per block, biases folded in g_hh0) ----------
        {
            float gi = __ldcg(&g_hh0[tid])         + sWih0[tid]         * x;
            float gf = __ldcg(&g_hh0[tid + H])     + sWih0[tid + H]     * x;
            float gg = __ldcg(&g_hh0[tid + 2 * H]) + sWih0[tid + 2 * H] * x;
            float go = __ldcg(&g_hh0[tid + 3 * H]) + sWih0[tid + 3 * H] * x;
            float c  = sigm(gf) * cs0[tid] + sigm(gi) * tanhf(gg);
            cs0[tid] = c;
            hs0[tid] = sigm(go) * tanhf(c);
        }
        __syncthreads();

        // ---------- owned layer-1 gates from smem wih1 ----------
        if (warp < GW1) {
            int e = warp >> 2, g = warp & 3;
            if (o0 + e < H) {
                float acc = dot1024(sW1 + (size_t)warp * H, h0v, lane);
                if (lane == 0)
                    sG[warp] = acc + sB1[warp] +
                               __ldcg(&g_hh1[(t + 1) & 1][(o0 + e) + g * H]);
            }
        }
        __syncthreads();

        // ---------- owned cell 1, publish h1 entries ----------
        if (tid < EPB && o0 + tid < H) {
            float gi = sG[tid * 4 + 0];
            float gf = sG[tid * 4 + 1];
            float gg = sG[tid * 4 + 2];
            float go = sG[tid * 4 + 3];
            float c  = sigm(gf) * sC1[tid] + sigm(gi) * tanhf(gg);
            sC1[tid] = c;
            __stcg(&g_h1[o0 + tid], sigm(go) * tanhf(c));
            __threadfence();
        }
        gsync(++barCnt);

        // ---------- load full h1 ----------
        hs1[tid] = __ldcg(&g_h1[tid]);
        __syncthreads();

        // ---------- fc (fp16, L2-resident, 2 rows/iter) ----------
        float wmax = 0.f;   // lane0-resident warp max of fp16 preds
        float* orow = out + (size_t)(t + 1) * V;
        for (int base = gw; base < V; base += 2 * TW) {
            int r0 = base, r1 = base + TW;
            bool has1 = (r1 < V);
            const uint4* w0 = (const uint4*)(g_wfc16 + (size_t)r0 * H);
            const uint4* w1 = (const uint4*)(g_wfc16 + (size_t)(has1 ? r1 : r0) * H);
            float a0 = 0.f, a1 = 0.f;
            #pragma unroll
            for (int k = 0; k < 4; ++k) {
                uint4 u0 = __ldg(&w0[lane + 32 * k]);
                uint4 u1 = __ldg(&w1[lane + 32 * k]);
                float4 ha = h1v[2 * (lane + 32 * k)];
                float4 hb = h1v[2 * (lane + 32 * k) + 1];
                const __half2* p0 = (const __half2*)&u0;
                const __half2* p1 = (const __half2*)&u1;
                float2 q;
                q = __half22float2(p0[0]); a0 = fmaf(q.x, ha.x, a0); a0 = fmaf(q.y, ha.y, a0);
                q = __half22float2(p0[1]); a0 = fmaf(q.x, ha.z, a0); a0 = fmaf(q.y, ha.w, a0);
                q = __half22float2(p0[2]); a0 = fmaf(q.x, hb.x, a0); a0 = fmaf(q.y, hb.y, a0);
                q = __half22float2(p0[3]); a0 = fmaf(q.x, hb.z, a0); a0 = fmaf(q.y, hb.w, a0);
                q = __half22float2(p1[0]); a1 = fmaf(q.x, ha.x, a1); a1 = fmaf(q.y, ha.y, a1);
                q = __half22float2(p1[1]); a1 = fmaf(q.x, ha.z, a1); a1 = fmaf(q.y, ha.w, a1);
                q = __half22float2(p1[2]); a1 = fmaf(q.x, hb.x, a1); a1 = fmaf(q.y, hb.y, a1);
                q = __half22float2(p1[3]); a1 = fmaf(q.x, hb.z, a1); a1 = fmaf(q.y, hb.w, a1);
            }
            #pragma unroll
            for (int off = 16; off; off >>= 1) {
                a0 += __shfl_down_sync(0xffffffffu, a0, off);
                a1 += __shfl_down_sync(0xffffffffu, a1, off);
            }
            if (lane == 0) {
                float p = fmaxf(a0 + bfc[r0], 0.0f);
                __stcs(&orow[r0], p);
                wmax = fmaxf(wmax, p);
                if (has1) {
                    float p1v = fmaxf(a1 + bfc[r1], 0.0f);
                    __stcs(&orow[r1], p1v);
                    wmax = fmaxf(wmax, p1v);
                }
            }
        }

        // ---------- whh0@h0_t, whh1@h1_t (L2-resident fp32) ----------
        float* hh1w = g_hh1[t & 1];
        for (int idx = gw; idx < 2 * FH; idx += TW) {
            if (idx < FH) {
                float acc = dot1024(whh0 + (size_t)idx * H, h0v, lane);
                if (lane == 0) __stcg(&g_hh0[idx], acc + bih0[idx] + bhh0[idx]);
            } else {
                int r = idx - FH;
                float acc = dot1024(whh1 + (size_t)r * H, h1v, lane);
                if (lane == 0) __stcg(&hh1w[r], acc);
            }
        }

        // ---------- exact per-block argmax + publish ----------
        if (t < SEQ - 2) {
            if (lane == 0) sRed[warp] = wmax;
            __syncthreads();
            if (tid == 0) {
                float mm = 0.f;
                #pragma unroll
                for (int w = 0; w < NW; ++w) mm = fmaxf(mm, sRed[w]);
                sMax = mm; sCnt = 0; sBest = 0ull;
            }
            __syncthreads();

            // rescan own rows for candidates within conservative fp16 margin
            float cutoff = sMax - (0.004f * fmaxf(sMax, 1.0f) + 0.004f);
            {
                int r = gw + lane * TW;
                if (r < V) {
                    float p = __ldcg(&orow[r]);
                    if (p >= cutoff) {
                        int pos = atomicAdd(&sCnt, 1);
                        if (pos < 64) sCand[pos] = r;
                    }
                }
            }
            __syncthreads();

            // recompute candidates in fp32, combine exact
            int ncand = sCnt < 64 ? sCnt : 64;
            for (int c = warp; c < ncand; c += NW) {
                int row = sCand[c];
                float acc = dot1024(wfc + (size_t)row * H, h1v, lane);
                if (lane == 0) {
                    float val = fmaxf(acc + bfc[row], 0.0f);
                    unsigned long long key =
                        ((unsigned long long)__float_as_uint(val) << 32) |
                        (unsigned)(0x7fffffff - row);
                    atomicMax(&sBest, key);
                }
            }
            __syncthreads();
            if (tid == 0) {
                __stcg(&g_part[bid], sBest);
                __threadfence();
                ((volatile unsigned*)g_done)[bid] = doneBase + (unsigned)(t + 1);
            }
        }
    }
}

extern "C" void kernel_launch(void* const* d_in, const int* in_sizes, int n_in,
                              void* d_out, int out_size) {
    const int*   y    = (const int*)  d_in[0];
    const float* ctx  = (const float*)d_in[1];
    const float* wih0 = (const float*)d_in[2];
    const float* whh0 = (const float*)d_in[3];
    const float* bih0 = (const float*)d_in[4];
    const float* bhh0 = (const float*)d_in[5];
    const float* wih1 = (const float*)d_in[6];
    const float* whh1 = (const float*)d_in[7];
    const float* bih1 = (const float*)d_in[8];
    const float* bhh1 = (const float*)d_in[9];
    const float* wfc  = (const float*)d_in[10];
    const float* bfc  = (const float*)d_in[11];
    float* out = (float*)d_out;

    const int dynSmem = (7168 + GW1 * H) * (int)sizeof(float);  // 143360 B
    static int attrSet = 0;
    if (!attrSet) {
        cudaFuncSetAttribute(decoder_kernel,
                             cudaFuncAttributeMaxDynamicSharedMemorySize, dynSmem);
        attrSet = 1;
    }

    conv_kernel<<<1024, 256>>>(wfc);
    decoder_kernel<<<GRID, NT, dynSmem>>>(y, ctx, wih0, whh0, bih0, bhh0,
                                          wih1, whh1, bih1, bhh1, wfc, bfc, out);
}